// round 3
// baseline (speedup 1.0000x reference)
#include <cuda_runtime.h>
#include <math.h>

#define H 1024
#define V 50257
#define L 2
#define ROWS_PB 8
#define NB_LOGITS ((V + ROWS_PB - 1) / ROWS_PB)  // 6283

// Scratch (device globals; no allocation allowed)
__device__ float g_x[H];              // GRU layer 0 output
__device__ float g_y[H];              // GRU layer 1 output (logits input)
__device__ float g_logits[V];
__device__ float g_pmax[NB_LOGITS];   // per-block online-softmax partials
__device__ float g_psum[NB_LOGITS];
__device__ float g_c[1];              // gmax + log(sumexp)
__device__ unsigned int g_counter;    // zero-initialized; last block resets to 0

__device__ __forceinline__ float warp_sum(float s) {
    #pragma unroll
    for (int o = 16; o > 0; o >>= 1) s += __shfl_xor_sync(0xFFFFFFFF, s, o);
    return s;
}
__device__ __forceinline__ float warp_max(float s) {
    #pragma unroll
    for (int o = 16; o > 0; o >>= 1) s = fmaxf(s, __shfl_xor_sync(0xFFFFFFFF, s, o));
    return s;
}
__device__ __forceinline__ float sigmoidf_(float v) {
    return 1.0f / (1.0f + __expf(-v));
}

// ---- GRU layer. grid = H blocks, 192 threads (6 warps). ----
template<bool FUSE_EMB>
__global__ __launch_bounds__(192) void gru_layer_kernel(
    const long long* __restrict__ idx,
    const float* __restrict__ emb,
    const float* __restrict__ x_vec,
    const float* __restrict__ h_prev,
    const float* __restrict__ w_ih,
    const float* __restrict__ w_hh,
    const float* __restrict__ b_ih,
    const float* __restrict__ b_hh,
    float* __restrict__ h_out_scratch,
    float* __restrict__ h_out_final)
{
    int j = blockIdx.x;
    int w = threadIdx.x >> 5;
    int lane = threadIdx.x & 31;

    const float* vec;
    bool do_relu = false;
    if (w < 3) {
        if (FUSE_EMB) { vec = emb + (size_t)idx[0] * H; do_relu = true; }
        else          { vec = x_vec; }
    } else {
        vec = h_prev;
    }
    const float* W = (w < 3) ? w_ih : w_hh;
    int row = (w % 3) * H + j;

    const float4* wr = reinterpret_cast<const float4*>(W + (size_t)row * H);
    const float4* vv = reinterpret_cast<const float4*>(vec);

    float4 a[8], b[8];
    #pragma unroll
    for (int k = 0; k < 8; k++) a[k] = __ldcs(&wr[lane + 32 * k]);
    #pragma unroll
    for (int k = 0; k < 8; k++) b[k] = __ldg(&vv[lane + 32 * k]);
    if (do_relu) {
        #pragma unroll
        for (int k = 0; k < 8; k++) {
            b[k].x = fmaxf(b[k].x, 0.0f); b[k].y = fmaxf(b[k].y, 0.0f);
            b[k].z = fmaxf(b[k].z, 0.0f); b[k].w = fmaxf(b[k].w, 0.0f);
        }
    }
    float s = 0.0f;
    #pragma unroll
    for (int k = 0; k < 8; k++)
        s += a[k].x * b[k].x + a[k].y * b[k].y + a[k].z * b[k].z + a[k].w * b[k].w;
    s = warp_sum(s);

    __shared__ float sm[6];
    if (lane == 0) sm[w] = s;
    __syncthreads();

    if (threadIdx.x == 0) {
        float i_r = sm[0] + b_ih[j];
        float i_z = sm[1] + b_ih[H + j];
        float i_n = sm[2] + b_ih[2 * H + j];
        float h_r = sm[3] + b_hh[j];
        float h_z = sm[4] + b_hh[H + j];
        float h_n = sm[5] + b_hh[2 * H + j];
        float r = sigmoidf_(i_r + h_r);
        float z = sigmoidf_(i_z + h_z);
        float n = tanhf(i_n + r * h_n);
        float hn = (1.0f - z) * n + z * h_prev[j];
        h_out_scratch[j] = hn;
        h_out_final[j]   = hn;
    }
}

// ---- logits + online-softmax partials + last-block global reduce ----
__global__ __launch_bounds__(256) void logits_kernel(
    const float* __restrict__ w_out,
    const float* __restrict__ b_out)
{
    __shared__ float xs[H];
    __shared__ float rowv[ROWS_PB];
    __shared__ bool is_last;
    __shared__ float red[8];

    for (int i = threadIdx.x; i < H; i += 256) xs[i] = g_y[i];
    __syncthreads();

    int wid = threadIdx.x >> 5;
    int lane = threadIdx.x & 31;
    int row = blockIdx.x * ROWS_PB + wid;

    float val = -INFINITY;
    if (row < V) {
        const float4* wr = reinterpret_cast<const float4*>(w_out + (size_t)row * H);
        const float4* vv = reinterpret_cast<const float4*>(xs);

        float4 a[8];
        #pragma unroll
        for (int k = 0; k < 8; k++) a[k] = __ldcs(&wr[lane + 32 * k]);
        float s = 0.0f;
        #pragma unroll
        for (int k = 0; k < 8; k++) {
            float4 b = vv[lane + 32 * k];
            s += a[k].x * b.x + a[k].y * b.y + a[k].z * b.z + a[k].w * b.w;
        }
        s = warp_sum(s);
        if (lane == 0) {
            val = s + b_out[row];
            g_logits[row] = val;
        }
    }
    if (lane == 0) rowv[wid] = val;
    __syncthreads();

    if (threadIdx.x == 0) {
        float m = -INFINITY;
        #pragma unroll
        for (int k = 0; k < ROWS_PB; k++) m = fmaxf(m, rowv[k]);
        float sum = 0.0f;
        #pragma unroll
        for (int k = 0; k < ROWS_PB; k++) {
            float v = rowv[k];
            if (v != -INFINITY) sum += expf(v - m);
        }
        g_pmax[blockIdx.x] = m;
        g_psum[blockIdx.x] = sum;
        __threadfence();
        unsigned int done = atomicAdd(&g_counter, 1u);
        is_last = (done == (unsigned int)(gridDim.x - 1));
    }
    __syncthreads();

    if (!is_last) return;

    // ---- last block: combine all partials into c ----
    int tid = threadIdx.x;
    float m = -INFINITY;
    for (int i = tid; i < NB_LOGITS; i += 256) m = fmaxf(m, g_pmax[i]);
    m = warp_max(m);
    if (lane == 0) red[wid] = m;
    __syncthreads();
    if (tid < 8) {
        float v = red[tid];
        #pragma unroll
        for (int o = 4; o > 0; o >>= 1) v = fmaxf(v, __shfl_xor_sync(0xFF, v, o));
        if (tid == 0) red[0] = v;
    }
    __syncthreads();
    float gmax = red[0];
    __syncthreads();

    float s = 0.0f;
    for (int i = tid; i < NB_LOGITS; i += 256)
        s += g_psum[i] * expf(g_pmax[i] - gmax);
    s = warp_sum(s);
    if (lane == 0) red[wid] = s;
    __syncthreads();
    if (tid < 8) {
        float v = red[tid];
        #pragma unroll
        for (int o = 4; o > 0; o >>= 1) v += __shfl_xor_sync(0xFF, v, o);
        if (tid == 0) {
            g_c[0] = gmax + logf(v);
            g_counter = 0;  // reset for next graph replay (deterministic)
        }
    }
}

// ---- write logprobs: out[i] = logits[i] - c, float4 ----
__global__ __launch_bounds__(256) void write_kernel(float* __restrict__ out) {
    float c = g_c[0];
    int i = blockIdx.x * 256 + threadIdx.x;
    const int V4 = V / 4;  // 12564
    if (i < V4) {
        float4 v = reinterpret_cast<const float4*>(g_logits)[i];
        v.x -= c; v.y -= c; v.z -= c; v.w -= c;
        reinterpret_cast<float4*>(out)[i] = v;
    }
    if (i == 0) out[V - 1] = g_logits[V - 1] - c;  // tail (V % 4 == 1)
}

extern "C" void kernel_launch(void* const* d_in, const int* in_sizes, int n_in,
                              void* d_out, int out_size) {
    const long long* idx  = (const long long*)d_in[0];
    const float* hidden   = (const float*)d_in[1];
    const float* emb      = (const float*)d_in[2];
    const float* w_ih     = (const float*)d_in[3];
    const float* w_hh     = (const float*)d_in[4];
    const float* b_ih     = (const float*)d_in[5];
    const float* b_hh     = (const float*)d_in[6];
    const float* w_out    = (const float*)d_in[7];
    const float* b_out    = (const float*)d_in[8];

    float* out = (float*)d_out;
    float* out_logprobs = out;       // [V]
    float* out_hidden   = out + V;   // [L, 1, H]

    float* g_x_ptr; cudaGetSymbolAddress((void**)&g_x_ptr, g_x);
    float* g_y_ptr; cudaGetSymbolAddress((void**)&g_y_ptr, g_y);

    gru_layer_kernel<true><<<H, 192>>>(idx, emb, nullptr, hidden,
                                       w_ih, w_hh, b_ih, b_hh,
                                       g_x_ptr, out_hidden);

    gru_layer_kernel<false><<<H, 192>>>(idx, emb, g_x_ptr, hidden + H,
                                        w_ih + 3 * H * H, w_hh + 3 * H * H,
                                        b_ih + 3 * H, b_hh + 3 * H,
                                        g_y_ptr, out_hidden + H);

    logits_kernel<<<NB_LOGITS, 256>>>(w_out, b_out);

    write_kernel<<<(V / 4 + 255) / 256, 256>>>(out_logprobs);
}